// round 7
// baseline (speedup 1.0000x reference)
#include <cuda_runtime.h>
#include <math.h>

#define HIDDEN 128
#define NGRAPH 4096
#define POOL_DIM (3 * HIDDEN)

__device__ float g_pooled[NGRAPH * POOL_DIM];   // 6 MB scratch
__device__ int   g_seg[NGRAPH + 1];             // segment starts (+sentinel)

__device__ __forceinline__ int batch_val(const int* __restrict__ w, int i, bool is64) {
    return is64 ? w[2 * i] : w[i];
}

// ---------------------------------------------------------------------------
// Phase 0: segment boundaries. One LDG per element; predecessor via shfl_up
// (lane 0 issues the single extra load). Empty graphs handled by gap loops.
// ---------------------------------------------------------------------------
__global__ void seg_kernel(const int* __restrict__ batch_raw, int n_nodes) {
    const bool is64 = (batch_raw[n_nodes - 1] == 0) && (batch_raw[n_nodes - 2] != 0);
    const int i = blockIdx.x * blockDim.x + threadIdx.x;
    const int lane = threadIdx.x & 31;

    int bi = 0;
    if (i < n_nodes) bi = batch_val(batch_raw, i, is64);
    int bp = __shfl_up_sync(0xffffffffu, bi, 1);   // full warp participates
    if (i >= n_nodes) return;
    if (lane == 0) bp = (i > 0) ? batch_val(batch_raw, i - 1, is64) : -1;
    if (i == 0) bp = -1;

    for (int g = bp + 1; g <= bi; g++) g_seg[g] = i;
    if (i == n_nodes - 1)
        for (int g = bi + 1; g <= NGRAPH; g++) g_seg[g] = n_nodes;
}

// ---------------------------------------------------------------------------
// Phase A: one block per graph; bounds from g_seg. 512 threads = 16 row-
// groups x 32 lanes; lane owns 4 channels via float4. Main loop: 4
// unpredicated independent 512B loads; single predicated tail iteration.
// ---------------------------------------------------------------------------
__global__ void __launch_bounds__(512)
pool_kernel(const float* __restrict__ x) {
    const int g     = blockIdx.x;
    const int start = g_seg[g];
    const int end   = g_seg[g + 1];

    const int lane = threadIdx.x & 31;
    const int h    = threadIdx.x >> 5;   // row group 0..15

    const float4* xv = (const float4*)x;

    const float NEG = -3.402823466e38f;
    float4 s0 = make_float4(0.f, 0.f, 0.f, 0.f), s1 = s0, s2 = s0, s3 = s0;
    float4 m0 = make_float4(NEG, NEG, NEG, NEG), m1 = m0, m2 = m0, m3 = m0;

    int i = start + h;
    for (; i + 48 < end; i += 64) {
        float4 v0 = __ldcs(xv + (size_t)i * 32 + lane);
        float4 v1 = __ldcs(xv + (size_t)(i + 16) * 32 + lane);
        float4 v2 = __ldcs(xv + (size_t)(i + 32) * 32 + lane);
        float4 v3 = __ldcs(xv + (size_t)(i + 48) * 32 + lane);
        s0.x += v0.x; s0.y += v0.y; s0.z += v0.z; s0.w += v0.w;
        m0.x = fmaxf(m0.x, v0.x); m0.y = fmaxf(m0.y, v0.y);
        m0.z = fmaxf(m0.z, v0.z); m0.w = fmaxf(m0.w, v0.w);
        s1.x += v1.x; s1.y += v1.y; s1.z += v1.z; s1.w += v1.w;
        m1.x = fmaxf(m1.x, v1.x); m1.y = fmaxf(m1.y, v1.y);
        m1.z = fmaxf(m1.z, v1.z); m1.w = fmaxf(m1.w, v1.w);
        s2.x += v2.x; s2.y += v2.y; s2.z += v2.z; s2.w += v2.w;
        m2.x = fmaxf(m2.x, v2.x); m2.y = fmaxf(m2.y, v2.y);
        m2.z = fmaxf(m2.z, v2.z); m2.w = fmaxf(m2.w, v2.w);
        s3.x += v3.x; s3.y += v3.y; s3.z += v3.z; s3.w += v3.w;
        m3.x = fmaxf(m3.x, v3.x); m3.y = fmaxf(m3.y, v3.y);
        m3.z = fmaxf(m3.z, v3.z); m3.w = fmaxf(m3.w, v3.w);
    }
    if (i < end) {
        const int i1 = i + 16, i2 = i + 32;
        const float f1 = (i1 < end) ? 1.0f : 0.0f;
        const float f2 = (i2 < end) ? 1.0f : 0.0f;
        const int c1 = (i1 < end) ? i1 : i;
        const int c2 = (i2 < end) ? i2 : i;
        float4 v0 = __ldcs(xv + (size_t)i  * 32 + lane);
        float4 v1 = __ldcs(xv + (size_t)c1 * 32 + lane);
        float4 v2 = __ldcs(xv + (size_t)c2 * 32 + lane);
        s0.x += v0.x; s0.y += v0.y; s0.z += v0.z; s0.w += v0.w;
        m0.x = fmaxf(m0.x, v0.x); m0.y = fmaxf(m0.y, v0.y);
        m0.z = fmaxf(m0.z, v0.z); m0.w = fmaxf(m0.w, v0.w);
        s1.x = fmaf(v1.x, f1, s1.x); s1.y = fmaf(v1.y, f1, s1.y);
        s1.z = fmaf(v1.z, f1, s1.z); s1.w = fmaf(v1.w, f1, s1.w);
        m1.x = fmaxf(m1.x, v1.x); m1.y = fmaxf(m1.y, v1.y);
        m1.z = fmaxf(m1.z, v1.z); m1.w = fmaxf(m1.w, v1.w);
        s2.x = fmaf(v2.x, f2, s2.x); s2.y = fmaf(v2.y, f2, s2.y);
        s2.z = fmaf(v2.z, f2, s2.z); s2.w = fmaf(v2.w, f2, s2.w);
        m2.x = fmaxf(m2.x, v2.x); m2.y = fmaxf(m2.y, v2.y);
        m2.z = fmaxf(m2.z, v2.z); m2.w = fmaxf(m2.w, v2.w);
    }

    float4 S = make_float4(s0.x + s1.x + s2.x + s3.x, s0.y + s1.y + s2.y + s3.y,
                           s0.z + s1.z + s2.z + s3.z, s0.w + s1.w + s2.w + s3.w);
    float4 M = make_float4(fmaxf(fmaxf(m0.x, m1.x), fmaxf(m2.x, m3.x)),
                           fmaxf(fmaxf(m0.y, m1.y), fmaxf(m2.y, m3.y)),
                           fmaxf(fmaxf(m0.z, m1.z), fmaxf(m2.z, m3.z)),
                           fmaxf(fmaxf(m0.w, m1.w), fmaxf(m2.w, m3.w)));

    __shared__ float4 s_sum[16][32];
    __shared__ float4 s_max[16][32];
    s_sum[h][lane] = S;
    s_max[h][lane] = M;
    __syncthreads();

    if (threadIdx.x < 128) {
        const int part = threadIdx.x >> 5;
        const int l    = threadIdx.x & 31;
        float4 a = s_sum[part][l], b = s_sum[part + 4][l],
               c = s_sum[part + 8][l], d = s_sum[part + 12][l];
        s_sum[part][l] = make_float4(a.x + b.x + c.x + d.x, a.y + b.y + c.y + d.y,
                                     a.z + b.z + c.z + d.z, a.w + b.w + c.w + d.w);
        float4 am = s_max[part][l], bm = s_max[part + 4][l],
               cm = s_max[part + 8][l], dm = s_max[part + 12][l];
        s_max[part][l] = make_float4(fmaxf(fmaxf(am.x, bm.x), fmaxf(cm.x, dm.x)),
                                     fmaxf(fmaxf(am.y, bm.y), fmaxf(cm.y, dm.y)),
                                     fmaxf(fmaxf(am.z, bm.z), fmaxf(cm.z, dm.z)),
                                     fmaxf(fmaxf(am.w, bm.w), fmaxf(cm.w, dm.w)));
    }
    __syncthreads();

    if (threadIdx.x < 32) {
        const int l = threadIdx.x;
        float4 a = s_sum[0][l], b = s_sum[1][l], c = s_sum[2][l], d = s_sum[3][l];
        float4 SS = make_float4(a.x + b.x + c.x + d.x, a.y + b.y + c.y + d.y,
                                a.z + b.z + c.z + d.z, a.w + b.w + c.w + d.w);
        float4 am = s_max[0][l], bm = s_max[1][l], cm = s_max[2][l], dm = s_max[3][l];
        float4 MM = make_float4(fmaxf(fmaxf(am.x, bm.x), fmaxf(cm.x, dm.x)),
                                fmaxf(fmaxf(am.y, bm.y), fmaxf(cm.y, dm.y)),
                                fmaxf(fmaxf(am.z, bm.z), fmaxf(cm.z, dm.z)),
                                fmaxf(fmaxf(am.w, bm.w), fmaxf(cm.w, dm.w)));
        const int cnt = end - start;
        const float inv = 1.0f / fmaxf((float)cnt, 1.0f);
        float4 mean = make_float4(SS.x * inv, SS.y * inv, SS.z * inv, SS.w * inv);
        if (cnt <= 0) MM = make_float4(0.f, 0.f, 0.f, 0.f);
        float4* o = (float4*)(g_pooled + (size_t)g * POOL_DIM);
        o[l]      = mean;
        o[32 + l] = MM;
        o[64 + l] = SS;
    }
}

// ---------------------------------------------------------------------------
// Phase B: fused GEMM + bias + LayerNorm + exact GELU. GT=16 -> grid=256.
// W stored PRE-DUPLICATED in smem ({w,w} pairs) so the inner loop per k is
// exactly: LDS.64 (w2) + LDS.128 (4 rows' p) + 2 packed f32x2 FMAs.
// Distance-2 software pipeline; KT=32 so the duplicated tile fits 48 KB.
// ---------------------------------------------------------------------------
__global__ void __launch_bounds__(512)
gemm_ln_gelu_kernel(const float* __restrict__ W, const float* __restrict__ bias,
                    const float* __restrict__ gamma, const float* __restrict__ beta,
                    float* __restrict__ out) {
    const int GT = 16;   // graph rows per block
    const int KT = 32;   // k tile

    // sW2 [32][128] float2 = 32 KB at 0; sP [32][20] = 2.5 KB; sH aliases sW2.
    __shared__ __align__(16) char smem_buf[KT * HIDDEN * 8 + KT * (GT + 4) * 4];
    float2 (*sW2)[HIDDEN]    = (float2(*)[HIDDEN])smem_buf;
    float  (*sP)[GT + 4]     = (float(*)[GT + 4])(smem_buf + KT * HIDDEN * 8);
    float  (*sH)[HIDDEN + 4] = (float(*)[HIDDEN + 4])smem_buf;

    const int g0 = blockIdx.x * GT;
    const int j  = threadIdx.x & (HIDDEN - 1);  // output column
    const int rg = threadIdx.x >> 7;            // 0..3: rows [rg*4, rg*4+4)

    unsigned long long acc2[2] = {0ull, 0ull};

    for (int kt = 0; kt < POOL_DIM; kt += KT) {
        __syncthreads();
        // W tile, duplicated: read float2 (cols c,c+1), write {wx,wx,wy,wy}
        {
            const float2* Wv = (const float2*)(W + (size_t)kt * HIDDEN);
#pragma unroll
            for (int idx = threadIdx.x; idx < KT * (HIDDEN / 2); idx += 512) {
                float2 w = Wv[idx];
                int k = idx >> 6, c2 = idx & 63;
                *(float4*)&sW2[k][c2 * 2] = make_float4(w.x, w.x, w.y, w.y);
            }
        }
        // pooled tile transposed (1 element per thread, coalesced along k)
        {
            int r = threadIdx.x >> 5, kk = threadIdx.x & (KT - 1);
            sP[kk][r] = g_pooled[(size_t)(g0 + r) * POOL_DIM + kt + kk];
        }
        __syncthreads();

        // distance-2 software pipeline (all LDS)
        unsigned long long w0 = *(const unsigned long long*)&sW2[0][j];
        unsigned long long w1 = *(const unsigned long long*)&sW2[1][j];
        ulonglong2 a0 = *(const ulonglong2*)&sP[0][rg * 4];
        ulonglong2 a1 = *(const ulonglong2*)&sP[1][rg * 4];

#pragma unroll
        for (int kk = 0; kk < KT - 2; kk += 2) {
            unsigned long long wn0 = *(const unsigned long long*)&sW2[kk + 2][j];
            ulonglong2 an0 = *(const ulonglong2*)&sP[kk + 2][rg * 4];
            asm("fma.rn.f32x2 %0, %1, %2, %0;" : "+l"(acc2[0]) : "l"(a0.x), "l"(w0));
            asm("fma.rn.f32x2 %0, %1, %2, %0;" : "+l"(acc2[1]) : "l"(a0.y), "l"(w0));
            unsigned long long wn1 = *(const unsigned long long*)&sW2[kk + 3][j];
            ulonglong2 an1 = *(const ulonglong2*)&sP[kk + 3][rg * 4];
            asm("fma.rn.f32x2 %0, %1, %2, %0;" : "+l"(acc2[0]) : "l"(a1.x), "l"(w1));
            asm("fma.rn.f32x2 %0, %1, %2, %0;" : "+l"(acc2[1]) : "l"(a1.y), "l"(w1));
            w0 = wn0; a0 = an0;
            w1 = wn1; a1 = an1;
        }
        asm("fma.rn.f32x2 %0, %1, %2, %0;" : "+l"(acc2[0]) : "l"(a0.x), "l"(w0));
        asm("fma.rn.f32x2 %0, %1, %2, %0;" : "+l"(acc2[1]) : "l"(a0.y), "l"(w0));
        asm("fma.rn.f32x2 %0, %1, %2, %0;" : "+l"(acc2[0]) : "l"(a1.x), "l"(w1));
        asm("fma.rn.f32x2 %0, %1, %2, %0;" : "+l"(acc2[1]) : "l"(a1.y), "l"(w1));
    }

    __syncthreads();   // sW2 reads done before sH alias writes

    float bj = bias[j];
#pragma unroll
    for (int r = 0; r < 2; r++) {
        float lo, hi;
        asm("mov.b64 {%0, %1}, %2;" : "=f"(lo), "=f"(hi) : "l"(acc2[r]));
        sH[rg * 4 + 2 * r][j]     = lo + bj;
        sH[rg * 4 + 2 * r + 1][j] = hi + bj;
    }
    __syncthreads();

    // LayerNorm + exact GELU: 16 warps, 1 row each; lane covers 4 columns
    const int warp = threadIdx.x >> 5, lane = threadIdx.x & 31;
    {
        const int row = warp;
        float v[4];
#pragma unroll
        for (int q = 0; q < 4; q++) v[q] = sH[row][lane + 32 * q];

        float s = v[0] + v[1] + v[2] + v[3];
#pragma unroll
        for (int o = 16; o > 0; o >>= 1) s += __shfl_xor_sync(0xffffffffu, s, o);
        float mu = s * (1.0f / 128.0f);

        float vs = 0.f;
#pragma unroll
        for (int q = 0; q < 4; q++) { float d = v[q] - mu; vs += d * d; }
#pragma unroll
        for (int o = 16; o > 0; o >>= 1) vs += __shfl_xor_sync(0xffffffffu, vs, o);
        float inv = rsqrtf(vs * (1.0f / 128.0f) + 1e-5f);

#pragma unroll
        for (int q = 0; q < 4; q++) {
            int col = lane + 32 * q;
            float y = (v[q] - mu) * inv * gamma[col] + beta[col];
            float ge = 0.5f * y * (1.0f + erff(y * 0.70710678118654752f));
            out[(size_t)(g0 + row) * HIDDEN + col] = ge;
        }
    }
}

// ---------------------------------------------------------------------------
extern "C" void kernel_launch(void* const* d_in, const int* in_sizes, int n_in,
                              void* d_out, int out_size) {
    int ix = -1;
    long long maxsz = -1;
    for (int i = 0; i < n_in; i++)
        if ((long long)in_sizes[i] > maxsz) { maxsz = in_sizes[i]; ix = i; }
    const int n_nodes = (int)(maxsz / HIDDEN);

    int ib = -1, iw = -1, vecs[3] = {-1, -1, -1}; int nv = 0;
    for (int i = 0; i < n_in; i++) {
        if (i == ix) continue;
        if (in_sizes[i] == n_nodes) ib = i;
        else if (in_sizes[i] == POOL_DIM * HIDDEN) iw = i;
        else if (in_sizes[i] == HIDDEN && nv < 3) vecs[nv++] = i;
    }

    const float* x     = (const float*)d_in[ix];
    const int*   batch = (const int*)d_in[ib];
    const float* W     = (const float*)d_in[iw];
    const float* b     = (const float*)d_in[vecs[0]];
    const float* gamma = (const float*)d_in[vecs[1]];
    const float* beta  = (const float*)d_in[vecs[2]];
    float* out = (float*)d_out;

    seg_kernel<<<(n_nodes + 511) / 512, 512>>>(batch, n_nodes);
    pool_kernel<<<NGRAPH, 512>>>(x);
    gemm_ln_gelu_kernel<<<NGRAPH / 16, 512>>>(W, b, gamma, beta, out);
}

// round 12
// speedup vs baseline: 1.0919x; 1.0919x over previous
#include <cuda_runtime.h>
#include <math.h>

#define HIDDEN 128
#define NGRAPH 4096
#define POOL_DIM (3 * HIDDEN)

__device__ float g_pooled[NGRAPH * POOL_DIM];   // 6 MB scratch
__device__ int   g_seg[NGRAPH + 1];             // segment starts (+sentinel)

__device__ __forceinline__ int batch_val(const int* __restrict__ w, int i, bool is64) {
    return is64 ? w[2 * i] : w[i];
}

// ---------------------------------------------------------------------------
// Phase 0: segment boundaries. Each thread owns 8 consecutive elements:
// 9 independent clamped loads (MLP 9) then a register-resident boundary scan.
// Latency-bound before (MLP 1); now 8-deep overlapped.
// ---------------------------------------------------------------------------
__global__ void seg_kernel(const int* __restrict__ batch_raw, int n_nodes) {
    const bool is64 = (batch_raw[n_nodes - 1] == 0) && (batch_raw[n_nodes - 2] != 0);
    const int base = (blockIdx.x * blockDim.x + threadIdx.x) * 8;
    if (base >= n_nodes) return;

    // all loads issued up front, clamped (independent -> overlapped)
    int prev = batch_val(batch_raw, (base > 0) ? base - 1 : 0, is64);
    if (base == 0) prev = -1;
    int b[8];
#pragma unroll
    for (int e = 0; e < 8; e++) {
        int idx = base + e;
        b[e] = batch_val(batch_raw, (idx < n_nodes) ? idx : (n_nodes - 1), is64);
    }

#pragma unroll
    for (int e = 0; e < 8; e++) {
        int idx = base + e;
        if (idx >= n_nodes) break;
        for (int g = prev + 1; g <= b[e]; g++) g_seg[g] = idx;
        if (idx == n_nodes - 1)
            for (int g = b[e] + 1; g <= NGRAPH; g++) g_seg[g] = n_nodes;
        prev = b[e];
    }
}

// ---------------------------------------------------------------------------
// Phase A (R6, unchanged): one block per graph; bounds from g_seg.
// 512 threads = 16 row-groups x 32 lanes; lane owns 4 channels via float4.
// ---------------------------------------------------------------------------
__global__ void __launch_bounds__(512)
pool_kernel(const float* __restrict__ x) {
    const int g     = blockIdx.x;
    const int start = g_seg[g];
    const int end   = g_seg[g + 1];

    const int lane = threadIdx.x & 31;
    const int h    = threadIdx.x >> 5;   // row group 0..15

    const float4* xv = (const float4*)x;

    const float NEG = -3.402823466e38f;
    float4 s0 = make_float4(0.f, 0.f, 0.f, 0.f), s1 = s0, s2 = s0, s3 = s0;
    float4 m0 = make_float4(NEG, NEG, NEG, NEG), m1 = m0, m2 = m0, m3 = m0;

    int i = start + h;
    for (; i + 48 < end; i += 64) {
        float4 v0 = __ldcs(xv + (size_t)i * 32 + lane);
        float4 v1 = __ldcs(xv + (size_t)(i + 16) * 32 + lane);
        float4 v2 = __ldcs(xv + (size_t)(i + 32) * 32 + lane);
        float4 v3 = __ldcs(xv + (size_t)(i + 48) * 32 + lane);
        s0.x += v0.x; s0.y += v0.y; s0.z += v0.z; s0.w += v0.w;
        m0.x = fmaxf(m0.x, v0.x); m0.y = fmaxf(m0.y, v0.y);
        m0.z = fmaxf(m0.z, v0.z); m0.w = fmaxf(m0.w, v0.w);
        s1.x += v1.x; s1.y += v1.y; s1.z += v1.z; s1.w += v1.w;
        m1.x = fmaxf(m1.x, v1.x); m1.y = fmaxf(m1.y, v1.y);
        m1.z = fmaxf(m1.z, v1.z); m1.w = fmaxf(m1.w, v1.w);
        s2.x += v2.x; s2.y += v2.y; s2.z += v2.z; s2.w += v2.w;
        m2.x = fmaxf(m2.x, v2.x); m2.y = fmaxf(m2.y, v2.y);
        m2.z = fmaxf(m2.z, v2.z); m2.w = fmaxf(m2.w, v2.w);
        s3.x += v3.x; s3.y += v3.y; s3.z += v3.z; s3.w += v3.w;
        m3.x = fmaxf(m3.x, v3.x); m3.y = fmaxf(m3.y, v3.y);
        m3.z = fmaxf(m3.z, v3.z); m3.w = fmaxf(m3.w, v3.w);
    }
    if (i < end) {
        const int i1 = i + 16, i2 = i + 32;
        const float f1 = (i1 < end) ? 1.0f : 0.0f;
        const float f2 = (i2 < end) ? 1.0f : 0.0f;
        const int c1 = (i1 < end) ? i1 : i;
        const int c2 = (i2 < end) ? i2 : i;
        float4 v0 = __ldcs(xv + (size_t)i  * 32 + lane);
        float4 v1 = __ldcs(xv + (size_t)c1 * 32 + lane);
        float4 v2 = __ldcs(xv + (size_t)c2 * 32 + lane);
        s0.x += v0.x; s0.y += v0.y; s0.z += v0.z; s0.w += v0.w;
        m0.x = fmaxf(m0.x, v0.x); m0.y = fmaxf(m0.y, v0.y);
        m0.z = fmaxf(m0.z, v0.z); m0.w = fmaxf(m0.w, v0.w);
        s1.x = fmaf(v1.x, f1, s1.x); s1.y = fmaf(v1.y, f1, s1.y);
        s1.z = fmaf(v1.z, f1, s1.z); s1.w = fmaf(v1.w, f1, s1.w);
        m1.x = fmaxf(m1.x, v1.x); m1.y = fmaxf(m1.y, v1.y);
        m1.z = fmaxf(m1.z, v1.z); m1.w = fmaxf(m1.w, v1.w);
        s2.x = fmaf(v2.x, f2, s2.x); s2.y = fmaf(v2.y, f2, s2.y);
        s2.z = fmaf(v2.z, f2, s2.z); s2.w = fmaf(v2.w, f2, s2.w);
        m2.x = fmaxf(m2.x, v2.x); m2.y = fmaxf(m2.y, v2.y);
        m2.z = fmaxf(m2.z, v2.z); m2.w = fmaxf(m2.w, v2.w);
    }

    float4 S = make_float4(s0.x + s1.x + s2.x + s3.x, s0.y + s1.y + s2.y + s3.y,
                           s0.z + s1.z + s2.z + s3.z, s0.w + s1.w + s2.w + s3.w);
    float4 M = make_float4(fmaxf(fmaxf(m0.x, m1.x), fmaxf(m2.x, m3.x)),
                           fmaxf(fmaxf(m0.y, m1.y), fmaxf(m2.y, m3.y)),
                           fmaxf(fmaxf(m0.z, m1.z), fmaxf(m2.z, m3.z)),
                           fmaxf(fmaxf(m0.w, m1.w), fmaxf(m2.w, m3.w)));

    __shared__ float4 s_sum[16][32];
    __shared__ float4 s_max[16][32];
    s_sum[h][lane] = S;
    s_max[h][lane] = M;
    __syncthreads();

    if (threadIdx.x < 128) {
        const int part = threadIdx.x >> 5;
        const int l    = threadIdx.x & 31;
        float4 a = s_sum[part][l], b = s_sum[part + 4][l],
               c = s_sum[part + 8][l], d = s_sum[part + 12][l];
        s_sum[part][l] = make_float4(a.x + b.x + c.x + d.x, a.y + b.y + c.y + d.y,
                                     a.z + b.z + c.z + d.z, a.w + b.w + c.w + d.w);
        float4 am = s_max[part][l], bm = s_max[part + 4][l],
               cm = s_max[part + 8][l], dm = s_max[part + 12][l];
        s_max[part][l] = make_float4(fmaxf(fmaxf(am.x, bm.x), fmaxf(cm.x, dm.x)),
                                     fmaxf(fmaxf(am.y, bm.y), fmaxf(cm.y, dm.y)),
                                     fmaxf(fmaxf(am.z, bm.z), fmaxf(cm.z, dm.z)),
                                     fmaxf(fmaxf(am.w, bm.w), fmaxf(cm.w, dm.w)));
    }
    __syncthreads();

    if (threadIdx.x < 32) {
        const int l = threadIdx.x;
        float4 a = s_sum[0][l], b = s_sum[1][l], c = s_sum[2][l], d = s_sum[3][l];
        float4 SS = make_float4(a.x + b.x + c.x + d.x, a.y + b.y + c.y + d.y,
                                a.z + b.z + c.z + d.z, a.w + b.w + c.w + d.w);
        float4 am = s_max[0][l], bm = s_max[1][l], cm = s_max[2][l], dm = s_max[3][l];
        float4 MM = make_float4(fmaxf(fmaxf(am.x, bm.x), fmaxf(cm.x, dm.x)),
                                fmaxf(fmaxf(am.y, bm.y), fmaxf(cm.y, dm.y)),
                                fmaxf(fmaxf(am.z, bm.z), fmaxf(cm.z, dm.z)),
                                fmaxf(fmaxf(am.w, bm.w), fmaxf(cm.w, dm.w)));
        const int cnt = end - start;
        const float inv = 1.0f / fmaxf((float)cnt, 1.0f);
        float4 mean = make_float4(SS.x * inv, SS.y * inv, SS.z * inv, SS.w * inv);
        if (cnt <= 0) MM = make_float4(0.f, 0.f, 0.f, 0.f);
        float4* o = (float4*)(g_pooled + (size_t)g * POOL_DIM);
        o[l]      = mean;
        o[32 + l] = MM;
        o[64 + l] = SS;
    }
}

// ---------------------------------------------------------------------------
// Phase B (R6, unchanged): fused GEMM + bias + LayerNorm + exact GELU.
// GT=16 -> grid=256; both operands in smem; distance-2 pipelined pure-LDS
// inner loop with packed f32x2 FMAs. sH aliases sW.
// ---------------------------------------------------------------------------
#define FMA2P(wv, pa)                                                           \
    do {                                                                        \
        unsigned long long w2_;                                                 \
        asm("mov.b64 %0, {%1, %1};" : "=l"(w2_) : "f"(wv));                     \
        asm("fma.rn.f32x2 %0, %1, %2, %0;" : "+l"(acc2[0]) : "l"((pa).x), "l"(w2_)); \
        asm("fma.rn.f32x2 %0, %1, %2, %0;" : "+l"(acc2[1]) : "l"((pa).y), "l"(w2_)); \
    } while (0)

__global__ void __launch_bounds__(512)
gemm_ln_gelu_kernel(const float* __restrict__ W, const float* __restrict__ bias,
                    const float* __restrict__ gamma, const float* __restrict__ beta,
                    float* __restrict__ out) {
    const int GT = 16;   // graph rows per block
    const int KT = 64;   // k tile

    __shared__ __align__(16) char smem_buf[KT * HIDDEN * 4 + KT * (GT + 4) * 4];
    float (*sW)[HIDDEN]     = (float(*)[HIDDEN])smem_buf;
    float (*sP)[GT + 4]     = (float(*)[GT + 4])(smem_buf + KT * HIDDEN * 4);
    float (*sH)[HIDDEN + 4] = (float(*)[HIDDEN + 4])smem_buf;

    const int g0 = blockIdx.x * GT;
    const int j  = threadIdx.x & (HIDDEN - 1);
    const int rg = threadIdx.x >> 7;            // 0..3: rows [rg*4, rg*4+4)

    unsigned long long acc2[2] = {0ull, 0ull};

    for (int kt = 0; kt < POOL_DIM; kt += KT) {
        __syncthreads();
        {
            const float4* Wv = (const float4*)(W + (size_t)kt * HIDDEN);
            float4* sWv = (float4*)sW;
#pragma unroll
            for (int idx = threadIdx.x; idx < KT * (HIDDEN / 4); idx += 512)
                sWv[idx] = Wv[idx];
        }
#pragma unroll
        for (int idx = threadIdx.x; idx < GT * KT; idx += 512) {
            int r = idx >> 6, kk = idx & (KT - 1);
            sP[kk][r] = g_pooled[(size_t)(g0 + r) * POOL_DIM + kt + kk];
        }
        __syncthreads();

        float w0 = sW[0][j];
        float w1 = sW[1][j];
        ulonglong2 a0 = *(const ulonglong2*)&sP[0][rg * 4];
        ulonglong2 a1 = *(const ulonglong2*)&sP[1][rg * 4];

#pragma unroll 8
        for (int kk = 0; kk < KT - 2; kk += 2) {
            float wn0 = sW[kk + 2][j];
            ulonglong2 an0 = *(const ulonglong2*)&sP[kk + 2][rg * 4];
            FMA2P(w0, a0);
            float wn1 = sW[kk + 3][j];
            ulonglong2 an1 = *(const ulonglong2*)&sP[kk + 3][rg * 4];
            FMA2P(w1, a1);
            w0 = wn0; a0 = an0;
            w1 = wn1; a1 = an1;
        }
        FMA2P(w0, a0);
        FMA2P(w1, a1);
    }

    __syncthreads();

    float bj = bias[j];
#pragma unroll
    for (int r = 0; r < 2; r++) {
        float lo, hi;
        asm("mov.b64 {%0, %1}, %2;" : "=f"(lo), "=f"(hi) : "l"(acc2[r]));
        sH[rg * 4 + 2 * r][j]     = lo + bj;
        sH[rg * 4 + 2 * r + 1][j] = hi + bj;
    }
    __syncthreads();

    const int warp = threadIdx.x >> 5, lane = threadIdx.x & 31;
    {
        const int row = warp;
        float v[4];
#pragma unroll
        for (int q = 0; q < 4; q++) v[q] = sH[row][lane + 32 * q];

        float s = v[0] + v[1] + v[2] + v[3];
#pragma unroll
        for (int o = 16; o > 0; o >>= 1) s += __shfl_xor_sync(0xffffffffu, s, o);
        float mu = s * (1.0f / 128.0f);

        float vs = 0.f;
#pragma unroll
        for (int q = 0; q < 4; q++) { float d = v[q] - mu; vs += d * d; }
#pragma unroll
        for (int o = 16; o > 0; o >>= 1) vs += __shfl_xor_sync(0xffffffffu, vs, o);
        float inv = rsqrtf(vs * (1.0f / 128.0f) + 1e-5f);

#pragma unroll
        for (int q = 0; q < 4; q++) {
            int col = lane + 32 * q;
            float y = (v[q] - mu) * inv * gamma[col] + beta[col];
            float ge = 0.5f * y * (1.0f + erff(y * 0.70710678118654752f));
            out[(size_t)(g0 + row) * HIDDEN + col] = ge;
        }
    }
}

// ---------------------------------------------------------------------------
extern "C" void kernel_launch(void* const* d_in, const int* in_sizes, int n_in,
                              void* d_out, int out_size) {
    int ix = -1;
    long long maxsz = -1;
    for (int i = 0; i < n_in; i++)
        if ((long long)in_sizes[i] > maxsz) { maxsz = in_sizes[i]; ix = i; }
    const int n_nodes = (int)(maxsz / HIDDEN);

    int ib = -1, iw = -1, vecs[3] = {-1, -1, -1}; int nv = 0;
    for (int i = 0; i < n_in; i++) {
        if (i == ix) continue;
        if (in_sizes[i] == n_nodes) ib = i;
        else if (in_sizes[i] == POOL_DIM * HIDDEN) iw = i;
        else if (in_sizes[i] == HIDDEN && nv < 3) vecs[nv++] = i;
    }

    const float* x     = (const float*)d_in[ix];
    const int*   batch = (const int*)d_in[ib];
    const float* W     = (const float*)d_in[iw];
    const float* b     = (const float*)d_in[vecs[0]];
    const float* gamma = (const float*)d_in[vecs[1]];
    const float* beta  = (const float*)d_in[vecs[2]];
    float* out = (float*)d_out;

    const int elems_per_thread = 8;
    const int threads = 256;
    const int grid = (n_nodes + elems_per_thread * threads - 1) / (elems_per_thread * threads);
    seg_kernel<<<grid, threads>>>(batch, n_nodes);
    pool_kernel<<<NGRAPH, 512>>>(x);
    gemm_ln_gelu_kernel<<<NGRAPH / 16, 512>>>(W, b, gamma, beta, out);
}

// round 13
// speedup vs baseline: 1.0944x; 1.0023x over previous
#include <cuda_runtime.h>
#include <math.h>

#define HIDDEN 128
#define NGRAPH 4096
#define POOL_DIM (3 * HIDDEN)

__device__ float g_pooled[NGRAPH * POOL_DIM];   // 6 MB scratch
__device__ int   g_seg[NGRAPH + 1];             // segment starts (+sentinel)

__device__ __forceinline__ int batch_val(const int* __restrict__ w, int i, bool is64) {
    return is64 ? w[2 * i] : w[i];
}

// ---------------------------------------------------------------------------
// Phase 0: segment boundaries. Each thread owns 8 consecutive elements loaded
// via 4 (int64) / 2 (int32) LDG.128s — contiguous 64B per thread, full sector
// use. Tail block uses the clamped scalar path. Boundary scan in registers.
// ---------------------------------------------------------------------------
__global__ void seg_kernel(const int* __restrict__ batch_raw, int n_nodes) {
    const bool is64 = (batch_raw[n_nodes - 1] == 0) && (batch_raw[n_nodes - 2] != 0);
    const int base = (blockIdx.x * blockDim.x + threadIdx.x) * 8;
    if (base >= n_nodes) return;

    int b[8];
    if (base + 8 <= n_nodes) {
        if (is64) {
            const int4* p = (const int4*)(batch_raw + 2 * base);  // 64B-aligned
            int4 q0 = p[0], q1 = p[1], q2 = p[2], q3 = p[3];
            b[0] = q0.x; b[1] = q0.z; b[2] = q1.x; b[3] = q1.z;
            b[4] = q2.x; b[5] = q2.z; b[6] = q3.x; b[7] = q3.z;
        } else {
            const int4* p = (const int4*)(batch_raw + base);      // 32B-aligned
            int4 q0 = p[0], q1 = p[1];
            b[0] = q0.x; b[1] = q0.y; b[2] = q0.z; b[3] = q0.w;
            b[4] = q1.x; b[5] = q1.y; b[6] = q1.z; b[7] = q1.w;
        }
    } else {
#pragma unroll
        for (int e = 0; e < 8; e++) {
            int idx = base + e;
            b[e] = batch_val(batch_raw, (idx < n_nodes) ? idx : (n_nodes - 1), is64);
        }
    }
    int prev = (base > 0) ? batch_val(batch_raw, base - 1, is64) : -1;

#pragma unroll
    for (int e = 0; e < 8; e++) {
        int idx = base + e;
        if (idx >= n_nodes) break;
        for (int g = prev + 1; g <= b[e]; g++) g_seg[g] = idx;
        if (idx == n_nodes - 1)
            for (int g = b[e] + 1; g <= NGRAPH; g++) g_seg[g] = n_nodes;
        prev = b[e];
    }
}

// ---------------------------------------------------------------------------
// Phase A (unchanged — at DRAM roofline): one block per graph; bounds from
// g_seg. 512 threads = 16 row-groups x 32 lanes; lane owns 4 channels.
// ---------------------------------------------------------------------------
__global__ void __launch_bounds__(512)
pool_kernel(const float* __restrict__ x) {
    const int g     = blockIdx.x;
    const int start = g_seg[g];
    const int end   = g_seg[g + 1];

    const int lane = threadIdx.x & 31;
    const int h    = threadIdx.x >> 5;   // row group 0..15

    const float4* xv = (const float4*)x;

    const float NEG = -3.402823466e38f;
    float4 s0 = make_float4(0.f, 0.f, 0.f, 0.f), s1 = s0, s2 = s0, s3 = s0;
    float4 m0 = make_float4(NEG, NEG, NEG, NEG), m1 = m0, m2 = m0, m3 = m0;

    int i = start + h;
    for (; i + 48 < end; i += 64) {
        float4 v0 = __ldcs(xv + (size_t)i * 32 + lane);
        float4 v1 = __ldcs(xv + (size_t)(i + 16) * 32 + lane);
        float4 v2 = __ldcs(xv + (size_t)(i + 32) * 32 + lane);
        float4 v3 = __ldcs(xv + (size_t)(i + 48) * 32 + lane);
        s0.x += v0.x; s0.y += v0.y; s0.z += v0.z; s0.w += v0.w;
        m0.x = fmaxf(m0.x, v0.x); m0.y = fmaxf(m0.y, v0.y);
        m0.z = fmaxf(m0.z, v0.z); m0.w = fmaxf(m0.w, v0.w);
        s1.x += v1.x; s1.y += v1.y; s1.z += v1.z; s1.w += v1.w;
        m1.x = fmaxf(m1.x, v1.x); m1.y = fmaxf(m1.y, v1.y);
        m1.z = fmaxf(m1.z, v1.z); m1.w = fmaxf(m1.w, v1.w);
        s2.x += v2.x; s2.y += v2.y; s2.z += v2.z; s2.w += v2.w;
        m2.x = fmaxf(m2.x, v2.x); m2.y = fmaxf(m2.y, v2.y);
        m2.z = fmaxf(m2.z, v2.z); m2.w = fmaxf(m2.w, v2.w);
        s3.x += v3.x; s3.y += v3.y; s3.z += v3.z; s3.w += v3.w;
        m3.x = fmaxf(m3.x, v3.x); m3.y = fmaxf(m3.y, v3.y);
        m3.z = fmaxf(m3.z, v3.z); m3.w = fmaxf(m3.w, v3.w);
    }
    if (i < end) {
        const int i1 = i + 16, i2 = i + 32;
        const float f1 = (i1 < end) ? 1.0f : 0.0f;
        const float f2 = (i2 < end) ? 1.0f : 0.0f;
        const int c1 = (i1 < end) ? i1 : i;
        const int c2 = (i2 < end) ? i2 : i;
        float4 v0 = __ldcs(xv + (size_t)i  * 32 + lane);
        float4 v1 = __ldcs(xv + (size_t)c1 * 32 + lane);
        float4 v2 = __ldcs(xv + (size_t)c2 * 32 + lane);
        s0.x += v0.x; s0.y += v0.y; s0.z += v0.z; s0.w += v0.w;
        m0.x = fmaxf(m0.x, v0.x); m0.y = fmaxf(m0.y, v0.y);
        m0.z = fmaxf(m0.z, v0.z); m0.w = fmaxf(m0.w, v0.w);
        s1.x = fmaf(v1.x, f1, s1.x); s1.y = fmaf(v1.y, f1, s1.y);
        s1.z = fmaf(v1.z, f1, s1.z); s1.w = fmaf(v1.w, f1, s1.w);
        m1.x = fmaxf(m1.x, v1.x); m1.y = fmaxf(m1.y, v1.y);
        m1.z = fmaxf(m1.z, v1.z); m1.w = fmaxf(m1.w, v1.w);
        s2.x = fmaf(v2.x, f2, s2.x); s2.y = fmaf(v2.y, f2, s2.y);
        s2.z = fmaf(v2.z, f2, s2.z); s2.w = fmaf(v2.w, f2, s2.w);
        m2.x = fmaxf(m2.x, v2.x); m2.y = fmaxf(m2.y, v2.y);
        m2.z = fmaxf(m2.z, v2.z); m2.w = fmaxf(m2.w, v2.w);
    }

    float4 S = make_float4(s0.x + s1.x + s2.x + s3.x, s0.y + s1.y + s2.y + s3.y,
                           s0.z + s1.z + s2.z + s3.z, s0.w + s1.w + s2.w + s3.w);
    float4 M = make_float4(fmaxf(fmaxf(m0.x, m1.x), fmaxf(m2.x, m3.x)),
                           fmaxf(fmaxf(m0.y, m1.y), fmaxf(m2.y, m3.y)),
                           fmaxf(fmaxf(m0.z, m1.z), fmaxf(m2.z, m3.z)),
                           fmaxf(fmaxf(m0.w, m1.w), fmaxf(m2.w, m3.w)));

    __shared__ float4 s_sum[16][32];
    __shared__ float4 s_max[16][32];
    s_sum[h][lane] = S;
    s_max[h][lane] = M;
    __syncthreads();

    if (threadIdx.x < 128) {
        const int part = threadIdx.x >> 5;
        const int l    = threadIdx.x & 31;
        float4 a = s_sum[part][l], b = s_sum[part + 4][l],
               c = s_sum[part + 8][l], d = s_sum[part + 12][l];
        s_sum[part][l] = make_float4(a.x + b.x + c.x + d.x, a.y + b.y + c.y + d.y,
                                     a.z + b.z + c.z + d.z, a.w + b.w + c.w + d.w);
        float4 am = s_max[part][l], bm = s_max[part + 4][l],
               cm = s_max[part + 8][l], dm = s_max[part + 12][l];
        s_max[part][l] = make_float4(fmaxf(fmaxf(am.x, bm.x), fmaxf(cm.x, dm.x)),
                                     fmaxf(fmaxf(am.y, bm.y), fmaxf(cm.y, dm.y)),
                                     fmaxf(fmaxf(am.z, bm.z), fmaxf(cm.z, dm.z)),
                                     fmaxf(fmaxf(am.w, bm.w), fmaxf(cm.w, dm.w)));
    }
    __syncthreads();

    if (threadIdx.x < 32) {
        const int l = threadIdx.x;
        float4 a = s_sum[0][l], b = s_sum[1][l], c = s_sum[2][l], d = s_sum[3][l];
        float4 SS = make_float4(a.x + b.x + c.x + d.x, a.y + b.y + c.y + d.y,
                                a.z + b.z + c.z + d.z, a.w + b.w + c.w + d.w);
        float4 am = s_max[0][l], bm = s_max[1][l], cm = s_max[2][l], dm = s_max[3][l];
        float4 MM = make_float4(fmaxf(fmaxf(am.x, bm.x), fmaxf(cm.x, dm.x)),
                                fmaxf(fmaxf(am.y, bm.y), fmaxf(cm.y, dm.y)),
                                fmaxf(fmaxf(am.z, bm.z), fmaxf(cm.z, dm.z)),
                                fmaxf(fmaxf(am.w, bm.w), fmaxf(cm.w, dm.w)));
        const int cnt = end - start;
        const float inv = 1.0f / fmaxf((float)cnt, 1.0f);
        float4 mean = make_float4(SS.x * inv, SS.y * inv, SS.z * inv, SS.w * inv);
        if (cnt <= 0) MM = make_float4(0.f, 0.f, 0.f, 0.f);
        float4* o = (float4*)(g_pooled + (size_t)g * POOL_DIM);
        o[l]      = mean;
        o[32 + l] = MM;
        o[64 + l] = SS;
    }
}

// ---------------------------------------------------------------------------
// Phase B: fused GEMM + bias + LayerNorm + exact GELU. GT=16 -> grid=256;
// KT=128 via DYNAMIC smem (74 KB/block, 2 blocks/SM): 3 tiles x 2 barriers
// instead of 6, 126-iteration pipelined runs. Inner loop identical to the
// proven R6 distance-2 pure-LDS pipeline with packed f32x2 FMAs.
// ---------------------------------------------------------------------------
#define GEMM_GT 16
#define GEMM_KT 128
#define GEMM_SMEM (GEMM_KT * HIDDEN * 4 + GEMM_KT * (GEMM_GT + 4) * 4)

#define FMA2P(wv, pa)                                                           \
    do {                                                                        \
        unsigned long long w2_;                                                 \
        asm("mov.b64 %0, {%1, %1};" : "=l"(w2_) : "f"(wv));                     \
        asm("fma.rn.f32x2 %0, %1, %2, %0;" : "+l"(acc2[0]) : "l"((pa).x), "l"(w2_)); \
        asm("fma.rn.f32x2 %0, %1, %2, %0;" : "+l"(acc2[1]) : "l"((pa).y), "l"(w2_)); \
    } while (0)

__global__ void __launch_bounds__(512)
gemm_ln_gelu_kernel(const float* __restrict__ W, const float* __restrict__ bias,
                    const float* __restrict__ gamma, const float* __restrict__ beta,
                    float* __restrict__ out) {
    const int GT = GEMM_GT;
    const int KT = GEMM_KT;

    extern __shared__ __align__(16) char smem_buf[];
    float (*sW)[HIDDEN]     = (float(*)[HIDDEN])smem_buf;                       // 64 KB
    float (*sP)[GT + 4]     = (float(*)[GT + 4])(smem_buf + KT * HIDDEN * 4);   // 10 KB
    float (*sH)[HIDDEN + 4] = (float(*)[HIDDEN + 4])smem_buf;                   // aliases sW

    const int g0 = blockIdx.x * GT;
    const int j  = threadIdx.x & (HIDDEN - 1);
    const int rg = threadIdx.x >> 7;            // 0..3: rows [rg*4, rg*4+4)

    unsigned long long acc2[2] = {0ull, 0ull};

    for (int kt = 0; kt < POOL_DIM; kt += KT) {
        __syncthreads();
        {
            const float4* Wv = (const float4*)(W + (size_t)kt * HIDDEN);
            float4* sWv = (float4*)sW;
#pragma unroll
            for (int idx = threadIdx.x; idx < KT * (HIDDEN / 4); idx += 512)
                sWv[idx] = Wv[idx];
        }
#pragma unroll
        for (int idx = threadIdx.x; idx < GT * KT; idx += 512) {
            int r = idx >> 7, kk = idx & (KT - 1);
            sP[kk][r] = g_pooled[(size_t)(g0 + r) * POOL_DIM + kt + kk];
        }
        __syncthreads();

        float w0 = sW[0][j];
        float w1 = sW[1][j];
        ulonglong2 a0 = *(const ulonglong2*)&sP[0][rg * 4];
        ulonglong2 a1 = *(const ulonglong2*)&sP[1][rg * 4];

#pragma unroll 8
        for (int kk = 0; kk < KT - 2; kk += 2) {
            float wn0 = sW[kk + 2][j];
            ulonglong2 an0 = *(const ulonglong2*)&sP[kk + 2][rg * 4];
            FMA2P(w0, a0);
            float wn1 = sW[kk + 3][j];
            ulonglong2 an1 = *(const ulonglong2*)&sP[kk + 3][rg * 4];
            FMA2P(w1, a1);
            w0 = wn0; a0 = an0;
            w1 = wn1; a1 = an1;
        }
        FMA2P(w0, a0);
        FMA2P(w1, a1);
    }

    __syncthreads();   // sW reads done before sH alias writes

    float bj = bias[j];
#pragma unroll
    for (int r = 0; r < 2; r++) {
        float lo, hi;
        asm("mov.b64 {%0, %1}, %2;" : "=f"(lo), "=f"(hi) : "l"(acc2[r]));
        sH[rg * 4 + 2 * r][j]     = lo + bj;
        sH[rg * 4 + 2 * r + 1][j] = hi + bj;
    }
    __syncthreads();

    const int warp = threadIdx.x >> 5, lane = threadIdx.x & 31;
    {
        const int row = warp;
        float v[4];
#pragma unroll
        for (int q = 0; q < 4; q++) v[q] = sH[row][lane + 32 * q];

        float s = v[0] + v[1] + v[2] + v[3];
#pragma unroll
        for (int o = 16; o > 0; o >>= 1) s += __shfl_xor_sync(0xffffffffu, s, o);
        float mu = s * (1.0f / 128.0f);

        float vs = 0.f;
#pragma unroll
        for (int q = 0; q < 4; q++) { float d = v[q] - mu; vs += d * d; }
#pragma unroll
        for (int o = 16; o > 0; o >>= 1) vs += __shfl_xor_sync(0xffffffffu, vs, o);
        float inv = rsqrtf(vs * (1.0f / 128.0f) + 1e-5f);

#pragma unroll
        for (int q = 0; q < 4; q++) {
            int col = lane + 32 * q;
            float y = (v[q] - mu) * inv * gamma[col] + beta[col];
            float ge = 0.5f * y * (1.0f + erff(y * 0.70710678118654752f));
            out[(size_t)(g0 + row) * HIDDEN + col] = ge;
        }
    }
}

// ---------------------------------------------------------------------------
extern "C" void kernel_launch(void* const* d_in, const int* in_sizes, int n_in,
                              void* d_out, int out_size) {
    int ix = -1;
    long long maxsz = -1;
    for (int i = 0; i < n_in; i++)
        if ((long long)in_sizes[i] > maxsz) { maxsz = in_sizes[i]; ix = i; }
    const int n_nodes = (int)(maxsz / HIDDEN);

    int ib = -1, iw = -1, vecs[3] = {-1, -1, -1}; int nv = 0;
    for (int i = 0; i < n_in; i++) {
        if (i == ix) continue;
        if (in_sizes[i] == n_nodes) ib = i;
        else if (in_sizes[i] == POOL_DIM * HIDDEN) iw = i;
        else if (in_sizes[i] == HIDDEN && nv < 3) vecs[nv++] = i;
    }

    const float* x     = (const float*)d_in[ix];
    const int*   batch = (const int*)d_in[ib];
    const float* W     = (const float*)d_in[iw];
    const float* b     = (const float*)d_in[vecs[0]];
    const float* gamma = (const float*)d_in[vecs[1]];
    const float* beta  = (const float*)d_in[vecs[2]];
    float* out = (float*)d_out;

    // raise dynamic-smem cap for the KT=128 W tile (idempotent, capture-safe)
    cudaFuncSetAttribute(gemm_ln_gelu_kernel,
                         cudaFuncAttributeMaxDynamicSharedMemorySize, GEMM_SMEM);

    const int elems_per_thread = 8;
    const int threads = 256;
    const int grid = (n_nodes + elems_per_thread * threads - 1) / (elems_per_thread * threads);
    seg_kernel<<<grid, threads>>>(batch, n_nodes);
    pool_kernel<<<NGRAPH, 512>>>(x);
    gemm_ln_gelu_kernel<<<NGRAPH / 16, 512, GEMM_SMEM>>>(W, b, gamma, beta, out);
}